// round 15
// baseline (speedup 1.0000x reference)
#include <cuda_runtime.h>
#include <cuda_bf16.h>
#include <cstdint>

// LinearRationalSpline forward — persistent cp.async pipeline, SLIM staging.
// inputs:  [16384, 64] f32, params: [16384, 64, 63] f32, out: [2*N] f32
//
// Key change vs the 12-warp plateau: stage ONLY w+h (32 floats/elem, padded
// to 33) in shared memory; d0/d1/lam are fetched by direct scattered __ldg
// once the bin index is known. Stage shrinks 16.1 KB -> 8.4 KB, so a
// double-buffered block costs 16.9 KB -> 12 resident blocks/SM = 24 warps
// (DRAM% has tracked warp count all session: 8w=69.6, 12w=77). Staging uses
// per-lane 4 B cp.async (lane-contiguous -> 128 B coalesced per warp-op)
// with commit_group/wait_group pipelining.

#define TPB   64
#define TILE  64
#define NBINS 16

#define ELEM_STRIDE 33                            // 32 floats + 1 pad (bank-safe)
#define STAGE_FLOATS (TILE * ELEM_STRIDE)         // 2112
#define STAGE_BYTES  (STAGE_FLOATS * 4)           // 8448
#define SMEM_TOTAL   (2 * STAGE_BYTES)            // 16896

__device__ __forceinline__ uint32_t smem_u32(const void* p) {
    uint32_t a;
    asm("{ .reg .u64 t; cvta.to.shared.u64 t, %1; cvt.u32.u64 %0, t; }"
        : "=r"(a) : "l"(p));
    return a;
}
__device__ __forceinline__ void cpa4(uint32_t dst, const void* src) {
    asm volatile("cp.async.ca.shared.global [%0], [%1], 4;"
                 :: "r"(dst), "l"(src) : "memory");
}
__device__ __forceinline__ void cpa_commit() {
    asm volatile("cp.async.commit_group;" ::: "memory");
}
__device__ __forceinline__ void cpa_wait1() {
    asm volatile("cp.async.wait_group 1;" ::: "memory");
}
__device__ __forceinline__ float rcp_approx(float x) {
    float r; asm("rcp.approx.f32 %0, %1;" : "=f"(r) : "f"(x)); return r;
}
__device__ __forceinline__ float sqrt_approx(float x) {
    float r; asm("sqrt.approx.f32 %0, %1;" : "=f"(r) : "f"(x)); return r;
}
__device__ __forceinline__ float softplus_f(float v) {
    return fmaxf(v, 0.0f) + __logf(1.0f + __expf(-fabsf(v)));
}

__global__ __launch_bounds__(TPB)
void lrs_kernel(const float* __restrict__ inputs,
                const float* __restrict__ params,
                float* __restrict__ out,
                int N, int numTiles)
{
    constexpr float BOUND = 3.0f;
    constexpr float MBW   = 0.001f;
    constexpr float MBH   = 0.001f;
    constexpr float MIND  = 0.001f;
    constexpr float MINL  = 0.025f;
    constexpr float EPSV  = 1e-6f;

    extern __shared__ float sp[];                 // [2][TILE][ELEM_STRIDE]
    const uint32_t sbase = smem_u32(sp);
    const int tid  = threadIdx.x;
    const int warp = tid >> 5;
    const int lane = tid & 31;

    const long long step = gridDim.x;

    // stage w+h of a full tile into buffer `buf` (each warp: 32 elements,
    // lane l copies float l of the element -> 128 B coalesced per warp-op)
    auto stage = [&](int buf, long long tile) {
        const float* src = params + tile * (long long)TILE * 63;
        const uint32_t dbase = sbase + (uint32_t)buf * STAGE_BYTES;
        #pragma unroll
        for (int i = 0; i < 32; i++) {
            const int el = warp * 32 + i;
            cpa4(dbase + (uint32_t)(el * ELEM_STRIDE + lane) * 4,
                 src + (long long)el * 63 + lane);
        }
    };

    // prologue: stage tiles t0, t1 (two cp.async groups, in order)
    {
        long long t0 = blockIdx.x;
        long long t1 = blockIdx.x + step;
        if (t0 < numTiles && (t0 + 1) * TILE <= N) stage(0, t0);
        cpa_commit();
        if (t1 < numTiles && (t1 + 1) * TILE <= N) stage(1, t1);
        cpa_commit();
    }

    // x prefetch queue (2 tiles ahead)
    float xq0 = 0.0f, xq1 = 0.0f;
    {
        long long t0 = blockIdx.x;
        long long t1 = blockIdx.x + step;
        if (t0 < numTiles) {
            long long i = t0 * TILE + tid; if (i >= N) i = N - 1;
            xq0 = __ldg(inputs + i);
        }
        if (t1 < numTiles) {
            long long i = t1 * TILE + tid; if (i >= N) i = N - 1;
            xq1 = __ldg(inputs + i);
        }
    }

    int stg = 0;

    for (long long tile = blockIdx.x; tile < numTiles; tile += step) {
        const long long e0 = tile * TILE;
        const int elems = (N - e0) < TILE ? (int)(N - e0) : TILE;
        float* buf = sp + (size_t)stg * STAGE_FLOATS;

        const float x = xq0;
        xq0 = xq1;
        {
            long long nt = tile + 2 * step;
            if (nt < numTiles) {
                long long i = nt * TILE + tid; if (i >= N) i = N - 1;
                xq1 = __ldg(inputs + i);
            }
        }

        if (elems == TILE) {
            cpa_wait1();           // oldest group (this buffer) complete
            __syncthreads();       // both warps' stages visible
        } else {
            // partial tail tile (never hit for N % 64 == 0)
            for (int i = tid; i < elems * 32; i += TPB) {
                const int el = i >> 5, fl = i & 31;
                buf[el * ELEM_STRIDE + fl] = params[(e0 + el) * 63 + fl];
            }
            __syncthreads();
        }

        if (tid < elems) {
            const float* __restrict__ p = buf + tid * ELEM_STRIDE;

            // softmax cumsums (two 8-chains + carry merge)
            float cw[NBINS], ch[NBINS];
            #pragma unroll
            for (int i = 0; i < NBINS; i++) cw[i] = __expf(p[i]);
            #pragma unroll
            for (int i = 0; i < NBINS; i++) ch[i] = __expf(p[16 + i]);
            #pragma unroll
            for (int i = 1; i < 8; i++)  { cw[i] += cw[i - 1];  ch[i] += ch[i - 1]; }
            #pragma unroll
            for (int i = 9; i < 16; i++) { cw[i] += cw[i - 1];  ch[i] += ch[i - 1]; }
            #pragma unroll
            for (int i = 8; i < 16; i++) { cw[i] += cw[7];      ch[i] += ch[7]; }

            const float Aw = (6.0f * (1.0f - 16.0f * MBW)) * rcp_approx(cw[NBINS - 1]);
            const float Ah = (6.0f * (1.0f - 16.0f * MBH)) * rcp_approx(ch[NBINS - 1]);

            // knots
            const float xm = x - EPSV;
            float kv[15], hv[15];
            #pragma unroll
            for (int i = 1; i <= 15; i++) {
                kv[i - 1] = fmaf(Aw, cw[i - 1], 6.0f * MBW * (float)i - BOUND);
                hv[i - 1] = fmaf(Ah, ch[i - 1], 6.0f * MBH * (float)i - BOUND);
            }

            // forward: count + last selected
            int cnt = 0;
            float cumw = -BOUND, ya = -BOUND;
            #pragma unroll
            for (int i = 0; i < 15; i++) {
                const bool c = kv[i] <= xm;
                cnt += c ? 1 : 0;
                cumw = c ? kv[i] : cumw;
                ya   = c ? hv[i] : ya;
            }
            cnt += (BOUND <= xm) ? 1 : 0;
            const int b = cnt > 15 ? 15 : cnt;

            // backward: first unselected (flagless)
            float wnext = BOUND, ykn = BOUND;
            #pragma unroll
            for (int i = 14; i >= 0; i--) {
                const bool u = kv[i] > xm;
                wnext = u ? kv[i] : wnext;
                ykn   = u ? hv[i] : ykn;
            }

            const float input_widths  = wnext - cumw;
            const float input_heights = ykn - ya;
            const float yb = input_heights + ya;

            // scattered global loads for d0/d1/lam (3 independent LDGs)
            const float* gp = params + (long long)(e0 + tid) * 63;
            const float d0r  = __ldg(gp + 32 + (b > 0  ? b - 1 : 0));
            const float d1r  = __ldg(gp + 32 + (b < 15 ? b     : 14));
            const float lraw = __ldg(gp + 47 + b);

            const float d0 = (b == 0)  ? (1.0f - MIND) : (MIND + softplus_f(d0r));
            const float d1 = (b == 15) ? (1.0f - MIND) : (MIND + softplus_f(d1r));

            const float sig = rcp_approx(1.0f + __expf(-lraw));
            const float lam = fmaf(1.0f - 2.0f * MINL, sig, MINL);

            // rational spline
            const float wbv = sqrt_approx(__fdividef(d0, d1));
            const float lwb = lam * wbv;
            const float wc_num = fmaf(lam, d0, (wbv - lwb) * d1);
            const float rcp_h  = rcp_approx(input_heights);
            const float wc = wc_num * input_widths * rcp_h;
            const float l1 = 1.0f - lam;
            const float yc = __fdividef(lwb * yb + l1 * ya, l1 + lwb);

            const float theta = __fdividef(x - cumw, input_widths);
            const bool ind = theta <= lam;
            const float ltheta = lam - theta;

            const float wcyc = wc * yc;
            const float wcyctheta = wcyc * theta;
            const float num = ind ? fmaf(ya, ltheta, wcyctheta)
                                  : (wcyc - wcyctheta) - (wbv * yb) * ltheta;
            const float wctheta = wc * theta;
            const float den = ind ? (wctheta + ltheta)
                                  : (wc - wctheta) - wbv * ltheta;
            const float outv = __fdividef(num, den);

            const float sel = ind ? lam * (yc - ya) : (wbv - lwb) * (yb - yc);
            const float lad = __logf(__fdividef(wc_num * sel,
                                     input_heights * (den * den)));

            const bool outside = (x < -BOUND) || (x > BOUND);
            const int e = (int)e0 + tid;
            out[e]     = outside ? x    : outv;
            out[N + e] = outside ? 0.0f : lad;
        }

        __syncthreads();   // both warps done reading this buffer

        // refill this buffer with tile + 2*step; commit unconditionally to
        // keep cp.async group ordering aligned with the wait_group count
        long long nt = tile + 2 * step;
        if (nt < numTiles && (nt + 1) * TILE <= N) stage(stg, nt);
        cpa_commit();
        stg ^= 1;
    }
}

extern "C" void kernel_launch(void* const* d_in, const int* in_sizes, int n_in,
                              void* d_out, int out_size) {
    const float* inputs = (const float*)d_in[0];
    const float* params = (const float*)d_in[1];
    float* out = (float*)d_out;
    const int N = in_sizes[0];
    const int numTiles = (N + TILE - 1) / TILE;

    cudaFuncSetAttribute(lrs_kernel,
                         cudaFuncAttributeMaxDynamicSharedMemorySize, SMEM_TOTAL);

    int dev = 0, nsm = 148;
    cudaGetDevice(&dev);
    cudaDeviceGetAttribute(&nsm, cudaDevAttrMultiProcessorCount, dev);
    int maxb = 1;
    cudaOccupancyMaxActiveBlocksPerMultiprocessor(&maxb, lrs_kernel, TPB, SMEM_TOTAL);
    if (maxb < 1) maxb = 1;

    long long grid = (long long)nsm * maxb;
    if (grid > numTiles) grid = numTiles;
    lrs_kernel<<<(int)grid, TPB, SMEM_TOTAL>>>(inputs, params, out, N, numTiles);
}